// round 1
// baseline (speedup 1.0000x reference)
#include <cuda_runtime.h>
#include <math.h>

#define BB 8
#define CC 64
#define H2 128
#define W2 128
#define PX (H2*W2)          // 16384
#define NSUB (BB*CC*PX)     // 8388608
#define NHEADS 4
#define HDIM 16

// ---------------- scratch (device globals; no runtime allocation) -----------
__device__ float g_ll[NSUB];
__device__ float g_lh[NSUB];
__device__ float g_hl[NSUB];
__device__ float g_hh[NSUB];
__device__ float g_h1[2*NSUB];   // high1 output, 128 channels
__device__ float g_filt[NSUB];
__device__ float g_t[NSUB];      // qkv 1x1 (v part only)
__device__ float g_vinp[NSUB];   // depthwise output
__device__ float g_z[NSUB];      // attention output, roll-back applied
__device__ float g_proj[NSUB];
__device__ float g_yh[3*NSUB];   // highout output, 192 channels

// ---------------- Haar DWT ---------------------------------------------------
__global__ void k_dwt(const float* __restrict__ x) {
    int idx = blockIdx.x * 256 + threadIdx.x;
    if (idx >= NSUB) return;
    int j  = idx & 127;
    int i  = (idx >> 7) & 127;
    int bc = idx >> 14;
    const float* xp = x + ((size_t)bc * 256 + 2 * i) * 256 + 2 * j;
    float2 t0 = *(const float2*)xp;
    float2 t1 = *(const float2*)(xp + 256);
    float a = t0.x, b = t0.y, c = t1.x, d = t1.y;
    g_ll[idx] = (a + b + c + d) * 0.5f;
    g_lh[idx] = (a - b + c - d) * 0.5f;
    g_hl[idx] = (a + b - c - d) * 0.5f;
    g_hh[idx] = (a - b - c + d) * 0.5f;
}

// ---------------- 3x3 conv, 64 in -> 64 out (one group), relu ----------------
// grid: (8, 8, B*4)  z = b*4 + kc ; block outputs 16 channels [kc*16, kc*16+16)
// block 256 thr: thread = (kg 0..7 -> 2 out ch, pxg 0..31 -> col lx, 8-row strip)
__global__ void __launch_bounds__(256) k_conv3x3(
        const float* __restrict__ in, float* __restrict__ out,
        const float* __restrict__ w, int outBstride) {
    __shared__ float st[324];    // 18x18 input tile (halo)
    __shared__ float swt[144];   // 16 ch x 9 weights for current ci
    int tx = blockIdx.x, ty = blockIdx.y;
    int bz = blockIdx.z;
    int b = bz >> 2, kc = bz & 3;
    int tid = threadIdx.x;
    int kg  = tid >> 5;
    int pxg = tid & 31;
    int lx  = pxg & 15;
    int ybase = (pxg >> 4) * 8;
    int gx0 = tx * 16 - 1;
    int gy0 = ty * 16 - 1;

    float acc0[8], acc1[8];
#pragma unroll
    for (int r = 0; r < 8; r++) { acc0[r] = 0.f; acc1[r] = 0.f; }

    for (int ci = 0; ci < 64; ci++) {
        __syncthreads();
        const float* ib = in + ((size_t)b * 64 + ci) * PX;
        for (int l = tid; l < 324; l += 256) {
            int ly = l / 18, lxx = l - ly * 18;
            int gy = gy0 + ly, gxx = gx0 + lxx;
            float v = 0.f;
            if ((unsigned)gy < 128u && (unsigned)gxx < 128u) v = ib[gy * 128 + gxx];
            st[l] = v;
        }
        for (int l = tid; l < 144; l += 256) {
            int kk = l / 9, e = l - kk * 9;
            swt[l] = w[((size_t)(kc * 16 + kk) * 64 + ci) * 9 + e];
        }
        __syncthreads();

        float w0[9], w1[9];
#pragma unroll
        for (int e = 0; e < 9; e++) { w0[e] = swt[kg * 18 + e]; w1[e] = swt[kg * 18 + 9 + e]; }

        float v[10][3];
#pragma unroll
        for (int r = 0; r < 10; r++)
#pragma unroll
            for (int c2 = 0; c2 < 3; c2++)
                v[r][c2] = st[(ybase + r) * 18 + lx + c2];

#pragma unroll
        for (int r = 0; r < 8; r++)
#pragma unroll
            for (int dy = 0; dy < 3; dy++)
#pragma unroll
                for (int dx = 0; dx < 3; dx++) {
                    float iv = v[r + dy][dx];
                    acc0[r] = fmaf(w0[dy * 3 + dx], iv, acc0[r]);
                    acc1[r] = fmaf(w1[dy * 3 + dx], iv, acc1[r]);
                }
    }

    int k0 = kc * 16 + kg * 2;
    float* op = out + (size_t)b * outBstride + (size_t)k0 * PX;
    int ox = tx * 16 + lx;
#pragma unroll
    for (int r = 0; r < 8; r++) {
        int oy = ty * 16 + ybase + r;
        op[oy * 128 + ox]      = fmaxf(acc0[r], 0.f);
        op[PX + oy * 128 + ox] = fmaxf(acc1[r], 0.f);
    }
}

// ---------------- 1x1 conv, KC in -> 64 out ----------------------------------
// grid: (32, B); block 256 thr, 2 adjacent pixels per thread (512 px / block)
__global__ void __launch_bounds__(256) k_conv1x1(
        const float* __restrict__ in, float* __restrict__ out,
        const float* __restrict__ w, int KC, int inBstride, int doRelu) {
    __shared__ float sw[8192];   // up to 64x128 weights
    int b = blockIdx.y;
    int tid = threadIdx.x;
    int nW = 64 * KC;
    for (int l = tid; l < nW; l += 256) sw[l] = w[l];
    __syncthreads();

    int p0 = blockIdx.x * 512 + tid * 2;
    const float* ip = in + (size_t)b * inBstride + p0;

    float2 acc[64];
#pragma unroll
    for (int o = 0; o < 64; o++) { acc[o].x = 0.f; acc[o].y = 0.f; }

    float2 iv = *(const float2*)ip;
    for (int k = 0; k < KC; k++) {
        float2 nv = make_float2(0.f, 0.f);
        if (k + 1 < KC) nv = *(const float2*)(ip + (size_t)(k + 1) * PX);
        const float* swk = sw + k;
#pragma unroll
        for (int o = 0; o < 64; o++) {
            float wv = swk[o * KC];
            acc[o].x = fmaf(wv, iv.x, acc[o].x);
            acc[o].y = fmaf(wv, iv.y, acc[o].y);
        }
        iv = nv;
    }

    float* op = out + (size_t)b * 64 * PX + p0;
#pragma unroll
    for (int o = 0; o < 64; o++) {
        float2 r = acc[o];
        if (doRelu) { r.x = fmaxf(r.x, 0.f); r.y = fmaxf(r.y, 0.f); }
        *(float2*)(op + (size_t)o * PX) = r;
    }
}

// ---------------- depthwise 3x3 (v channels only) ----------------------------
__global__ void k_dw(const float* __restrict__ in, float* __restrict__ out,
                     const float* __restrict__ w) {
    int idx = blockIdx.x * 256 + threadIdx.x;
    if (idx >= NSUB) return;
    int x = idx & 127;
    int y = (idx >> 7) & 127;
    int bc = idx >> 14;
    int c = bc & 63;
    const float* wp = w + c * 9;
    const float* ip = in + (size_t)bc * PX;
    float acc = 0.f;
#pragma unroll
    for (int dy = 0; dy < 3; dy++) {
        int yy = y + dy - 1;
        if ((unsigned)yy >= 128u) continue;
#pragma unroll
        for (int dx = 0; dx < 3; dx++) {
            int xx = x + dx - 1;
            if ((unsigned)xx >= 128u) continue;
            acc = fmaf(wp[dy * 3 + dx], ip[yy * 128 + xx], acc);
        }
    }
    out[idx] = acc;
}

// ---------------- window attention (shift fused in gather/scatter) -----------
// grid: 2048 = B*16*16 windows; block 256 thr: thread = (head, token)
__global__ void __launch_bounds__(256) k_attn(
        const float* __restrict__ table, const float* __restrict__ temp) {
    __shared__ float qs[64][64];   // [channel][token]
    __shared__ float vsm[64][64];
    __shared__ float scl[256];
    __shared__ float tbl[900];
    __shared__ float stemp[4];

    int bw = blockIdx.x;
    int b  = bw >> 8;
    int wr = (bw >> 4) & 15;
    int wc = bw & 15;
    int tid = threadIdx.x;

    if (tid < 4) stemp[tid] = temp[tid];
    for (int l = tid; l < 900; l += 256) tbl[l] = table[l];

    for (int l = tid; l < 4096; l += 256) {
        int c = l >> 6, n = l & 63;
        int y = n >> 3, x = n & 7;
        size_t base = ((size_t)b * 64 + c) * PX;
        int qy = (wr * 8 + y + 4) & 127;
        int qx = (wc * 8 + x + 4) & 127;
        qs[c][n] = g_ll[base + qy * 128 + qx];
        int vy = wr * 8 + y, vx = wc * 8 + x;
        float vi = g_vinp[base + vy * 128 + vx];
        float ft = g_filt[base + vy * 128 + vx];
        vsm[c][n] = vi * (1.0f + ft);
    }
    __syncthreads();

    {
        int h = tid >> 6, n = tid & 63;
        float s = 0.f;
#pragma unroll
        for (int d = 0; d < 16; d++) { float v = qs[h * 16 + d][n]; s += v * v; }
        scl[tid] = 1.0f / fmaxf(sqrtf(s), 1e-12f);
    }
    __syncthreads();

    int h = tid >> 6, n = tid & 63;
    int yn = n >> 3, xn = n & 7;
    float myscl = scl[tid];
    float tph = stemp[h];

    float qn[16];
#pragma unroll
    for (int d = 0; d < 16; d++) qn[d] = qs[h * 16 + d][n] * myscl;

    float a[64];
    for (int m = 0; m < 64; m++) {
        float s = 0.f;
#pragma unroll
        for (int d = 0; d < 16; d++) s = fmaf(qn[d], qs[h * 16 + d][m], s);
        s *= scl[(h << 6) | m];
        int ym = m >> 3, xm = m & 7;
        int ridx = (yn - ym + 7) * 15 + (xn - xm + 7);
        a[m] = (s + tbl[ridx * 4 + h]) * tph;
    }

    float mx = -1e30f;
#pragma unroll
    for (int m = 0; m < 64; m++) mx = fmaxf(mx, a[m]);
    float sum = 0.f;
#pragma unroll
    for (int m = 0; m < 64; m++) { float e = expf(a[m] - mx); a[m] = e; sum += e; }
    float inv = 1.0f / sum;

    float o[16];
#pragma unroll
    for (int d = 0; d < 16; d++) o[d] = 0.f;
    for (int m = 0; m < 64; m++) {
        float am = a[m] * inv;
#pragma unroll
        for (int d = 0; d < 16; d++) o[d] = fmaf(vsm[h * 16 + d][m], am, o[d]);
    }

    int oy = (wr * 8 + yn + 4) & 127;
    int ox = (wc * 8 + xn + 4) & 127;
#pragma unroll
    for (int d = 0; d < 16; d++)
        g_z[((size_t)b * 64 + h * 16 + d) * PX + oy * 128 + ox] = o[d];
}

// ---------------- inverse Haar DWT -------------------------------------------
__global__ void k_idwt(float* __restrict__ out) {
    int idx = blockIdx.x * 256 + threadIdx.x;
    if (idx >= NSUB) return;
    int j  = idx & 127;
    int i  = (idx >> 7) & 127;
    int bc = idx >> 14;
    int b = bc >> 6, c = bc & 63;
    int p = i * 128 + j;
    float ll = g_proj[idx];
    const float* yb = g_yh + (size_t)b * 192 * PX + p;
    float lh = yb[(size_t)c * PX];
    float hl = yb[(size_t)(64 + c) * PX];
    float hh = yb[(size_t)(128 + c) * PX];
    float a  = (ll + lh + hl + hh) * 0.5f;
    float b2 = (ll - lh + hl - hh) * 0.5f;
    float c2 = (ll + lh - hl - hh) * 0.5f;
    float d2 = (ll - lh - hl + hh) * 0.5f;
    float* op = out + ((size_t)bc * 256 + 2 * i) * 256 + 2 * j;
    *(float2*)op         = make_float2(a, b2);
    *(float2*)(op + 256) = make_float2(c2, d2);
}

// ---------------- launcher ---------------------------------------------------
extern "C" void kernel_launch(void* const* d_in, const int* in_sizes, int n_in,
                              void* d_out, int out_size) {
    const float* x         = (const float*)d_in[0];
    const float* temperature = (const float*)d_in[1];
    const float* rel_bias  = (const float*)d_in[2];
    const float* w_high1   = (const float*)d_in[3];
    const float* w_high2   = (const float*)d_in[4];
    const float* w_highout = (const float*)d_in[5];
    const float* w_qkv     = (const float*)d_in[6];
    const float* w_dwconv  = (const float*)d_in[7];
    const float* w_proj    = (const float*)d_in[8];
    float* out = (float*)d_out;

    float *p_ll, *p_lh, *p_hl, *p_hh, *p_h1, *p_filt, *p_t, *p_vinp, *p_z, *p_proj, *p_yh;
    cudaGetSymbolAddress((void**)&p_ll, g_ll);
    cudaGetSymbolAddress((void**)&p_lh, g_lh);
    cudaGetSymbolAddress((void**)&p_hl, g_hl);
    cudaGetSymbolAddress((void**)&p_hh, g_hh);
    cudaGetSymbolAddress((void**)&p_h1, g_h1);
    cudaGetSymbolAddress((void**)&p_filt, g_filt);
    cudaGetSymbolAddress((void**)&p_t, g_t);
    cudaGetSymbolAddress((void**)&p_vinp, g_vinp);
    cudaGetSymbolAddress((void**)&p_z, g_z);
    cudaGetSymbolAddress((void**)&p_proj, g_proj);
    cudaGetSymbolAddress((void**)&p_yh, g_yh);

    int nb = (NSUB + 255) / 256;
    dim3 g3(8, 8, BB * 4);
    dim3 g11(PX / 512, BB);

    // 1. DWT
    k_dwt<<<nb, 256>>>(x);
    // 2. high1 grouped 3x3 (group0: lh, group1: hl) -> g_h1[128ch], relu
    k_conv3x3<<<g3, 256>>>(p_lh, p_h1,            w_high1,               128 * PX);
    k_conv3x3<<<g3, 256>>>(p_hl, p_h1 + 64 * PX,  w_high1 + 64 * 64 * 9, 128 * PX);
    // 3. high2 1x1 (128->64, relu) -> filt
    k_conv1x1<<<g11, 256>>>(p_h1, p_filt, w_high2, 128, 128 * PX, 1);
    // 4. qkv 1x1 (v slice only: rows 128..191) -> t
    k_conv1x1<<<g11, 256>>>(p_ll, p_t, w_qkv + 128 * 64, 64, 64 * PX, 0);
    // 5. depthwise 3x3 (v channels) -> v_inp
    k_dw<<<nb, 256>>>(p_t, p_vinp, w_dwconv + 128 * 9);
    // 6. shifted-window attention (roll fused) -> z
    k_attn<<<2048, 256>>>(rel_bias, temperature);
    // 7. proj 1x1 -> proj
    k_conv1x1<<<g11, 256>>>(p_z, p_proj, w_proj, 64, 64 * PX, 0);
    // 8. highout grouped 3x3 (lh/hl/hh), relu -> yh[192ch]
    k_conv3x3<<<g3, 256>>>(p_lh, p_yh,             w_highout,                   192 * PX);
    k_conv3x3<<<g3, 256>>>(p_hl, p_yh + 64 * PX,   w_highout + 64 * 64 * 9,     192 * PX);
    k_conv3x3<<<g3, 256>>>(p_hh, p_yh + 128 * PX,  w_highout + 2 * 64 * 64 * 9, 192 * PX);
    // 9. IDWT -> out
    k_idwt<<<nb, 256>>>(out);
}

// round 3
// speedup vs baseline: 2.3413x; 2.3413x over previous
#include <cuda_runtime.h>
#include <math.h>

#define BB 8
#define CC 64
#define H2 128
#define W2 128
#define PX (H2*W2)          // 16384
#define NSUB (BB*CC*PX)     // 8388608
#define NHEADS 4
#define HDIM 16

#define IN_STR 344          // smem stride for 18x18 input tile (bank-conflict-free)
#define IN1_STR 264         // smem stride for 256-px 1x1 tile
#define W_STR 72            // smem stride for weight o-dim

// ---------------- scratch (device globals; no runtime allocation) -----------
__device__ float g_ll[NSUB];
__device__ float g_lh[NSUB];
__device__ float g_hl[NSUB];
__device__ float g_hh[NSUB];
__device__ float g_h1[2*NSUB];   // high1 output, 128 channels
__device__ float g_filt[NSUB];
__device__ float g_t[NSUB];      // qkv 1x1 (v part only)
__device__ float g_vinp[NSUB];   // depthwise output
__device__ float g_z[NSUB];      // attention output, roll-back applied
__device__ float g_proj[NSUB];
__device__ float g_yh[3*NSUB];   // highout output, 192 channels

// ---------------- helpers ----------------------------------------------------
__device__ __forceinline__ unsigned f2tf(float f) {
    unsigned u;
    asm("cvt.rna.tf32.f32 %0, %1;" : "=r"(u) : "f"(f));
    return u;
}

#define MMA_TF32(c0,c1,c2,c3,a0,a1,a2,a3,b0,b1)                                \
    asm volatile("mma.sync.aligned.m16n8k8.row.col.f32.tf32.tf32.f32 "          \
        "{%0,%1,%2,%3}, {%4,%5,%6,%7}, {%8,%9}, {%0,%1,%2,%3};\n"               \
        : "+f"(c0), "+f"(c1), "+f"(c2), "+f"(c3)                                \
        : "r"(a0), "r"(a1), "r"(a2), "r"(a3), "r"(b0), "r"(b1))

// ---------------- Haar DWT ---------------------------------------------------
__global__ void k_dwt(const float* __restrict__ x) {
    int idx = blockIdx.x * 256 + threadIdx.x;
    if (idx >= NSUB) return;
    int j  = idx & 127;
    int i  = (idx >> 7) & 127;
    int bc = idx >> 14;
    const float* xp = x + ((size_t)bc * 256 + 2 * i) * 256 + 2 * j;
    float2 t0 = *(const float2*)xp;
    float2 t1 = *(const float2*)(xp + 256);
    float a = t0.x, b = t0.y, c = t1.x, d = t1.y;
    g_ll[idx] = (a + b + c + d) * 0.5f;
    g_lh[idx] = (a - b + c - d) * 0.5f;
    g_hl[idx] = (a + b - c - d) * 0.5f;
    g_hh[idx] = (a - b - c + d) * 0.5f;
}

// ---------------- 3x3 conv 64->64 via tf32 MMA, fused relu -------------------
// grid (8,8,B); block 256 thr (8 warps). Per block: M=64 outch, N=256 px tile.
// K loop: 8 ci-chunks of 8, x 9 taps -> one m16n8k8 k-slab per (chunk,tap).
__global__ void __launch_bounds__(256, 2) k_conv3x3_mma(
        const float* __restrict__ in, float* __restrict__ out,
        const float* __restrict__ w, int outBstride) {
    __shared__ unsigned sIn[8 * IN_STR];        // 8 ci x 324 (18x18 halo), tf32
    __shared__ unsigned sW[9 * 8 * W_STR];      // [tap][ci][o]

    int tx = blockIdx.x, ty = blockIdx.y, b = blockIdx.z;
    int tid  = threadIdx.x;
    int wp   = tid >> 5;
    int lane = tid & 31;
    int gid  = lane >> 2, tg = lane & 3;
    int mw    = wp & 3;       // m-tile (16 outch)
    int nhalf = wp >> 2;      // n half (128 px)
    int gx0 = tx * 16 - 1, gy0 = ty * 16 - 1;

    int posB[16];
#pragma unroll
    for (int nt = 0; nt < 16; nt++) {
        int n = nhalf * 128 + nt * 8 + gid;
        posB[nt] = (n >> 4) * 18 + (n & 15);
    }

    float acc[16][4];
#pragma unroll
    for (int t = 0; t < 16; t++) { acc[t][0] = acc[t][1] = acc[t][2] = acc[t][3] = 0.f; }

    for (int ch = 0; ch < 8; ch++) {
        __syncthreads();
        // stage 8 input channels (18x18 with zero halo), tf32-converted
        const float* ib = in + ((size_t)b * 64 + ch * 8) * PX;
        for (int l = tid; l < 8 * 324; l += 256) {
            int ciL = l / 324, pos = l - ciL * 324;
            int ly = pos / 18, lx = pos - ly * 18;
            int gy = gy0 + ly, gx = gx0 + lx;
            float v = 0.f;
            if ((unsigned)gy < 128u && (unsigned)gx < 128u) v = ib[(size_t)ciL * PX + gy * 128 + gx];
            sIn[ciL * IN_STR + pos] = f2tf(v);
        }
        // stage weights: sW[(d*8+ciL)*W_STR + o] = w[(o*64 + ch*8+ciL)*9 + d]
        for (int l = tid; l < 64 * 72; l += 256) {
            int o = l / 72, r = l - o * 72;
            int ciL = r / 9, d = r - ciL * 9;
            sW[(d * 8 + ciL) * W_STR + o] = f2tf(w[((size_t)o * 64 + ch * 8 + ciL) * 9 + d]);
        }
        __syncthreads();

#pragma unroll
        for (int d = 0; d < 9; d++) {
            int dOff = (d / 3) * 18 + (d % 3);
            const unsigned* aw = sW + (d * 8 + tg) * W_STR + mw * 16 + gid;
            unsigned a0 = aw[0];
            unsigned a1 = aw[8];
            unsigned a2 = aw[4 * W_STR];
            unsigned a3 = aw[4 * W_STR + 8];
            const unsigned* bw = sIn + tg * IN_STR + dOff;
#pragma unroll
            for (int nt = 0; nt < 16; nt++) {
                unsigned b0 = bw[posB[nt]];
                unsigned b1 = bw[posB[nt] + 4 * IN_STR];
                MMA_TF32(acc[nt][0], acc[nt][1], acc[nt][2], acc[nt][3],
                         a0, a1, a2, a3, b0, b1);
            }
        }
    }

    float* ob = out + (size_t)b * outBstride;
    int o = mw * 16 + gid;
#pragma unroll
    for (int nt = 0; nt < 16; nt++) {
        int n = nhalf * 128 + nt * 8 + tg * 2;
        int gy = ty * 16 + (n >> 4), gx = tx * 16 + (n & 15);
        float* p0 = ob + (size_t)o * PX + gy * 128 + gx;
        *(float2*)p0 = make_float2(fmaxf(acc[nt][0], 0.f), fmaxf(acc[nt][1], 0.f));
        float* p1 = p0 + 8 * PX;
        *(float2*)p1 = make_float2(fmaxf(acc[nt][2], 0.f), fmaxf(acc[nt][3], 0.f));
    }
}

// ---------------- 1x1 conv KC->64 via tf32 MMA -------------------------------
// grid (PX/256, B); block 256 thr. M=64 outch, N=256 contiguous px, K=KC.
__global__ void __launch_bounds__(256, 2) k_conv1x1_mma(
        const float* __restrict__ in, float* __restrict__ out,
        const float* __restrict__ w, int KC, int inBstride, int doRelu) {
    __shared__ unsigned sIn[16 * IN1_STR];   // 16 ci x 256 px
    __shared__ unsigned sW[16 * W_STR];      // [ci][o]

    int b = blockIdx.y;
    int p0blk = blockIdx.x * 256;
    int tid  = threadIdx.x;
    int wp   = tid >> 5;
    int lane = tid & 31;
    int gid  = lane >> 2, tg = lane & 3;
    int mw    = wp & 3;
    int nhalf = wp >> 2;

    const float* ib = in + (size_t)b * inBstride + p0blk;

    float acc[16][4];
#pragma unroll
    for (int t = 0; t < 16; t++) { acc[t][0] = acc[t][1] = acc[t][2] = acc[t][3] = 0.f; }

    int nch = KC >> 4;
    for (int ch = 0; ch < nch; ch++) {
        __syncthreads();
        for (int l = tid; l < 16 * 256; l += 256) {
            int ciL = l >> 8, p = l & 255;
            sIn[ciL * IN1_STR + p] = f2tf(ib[(size_t)(ch * 16 + ciL) * PX + p]);
        }
        for (int l = tid; l < 1024; l += 256) {
            int o = l & 63, ciL = l >> 6;
            sW[ciL * W_STR + o] = f2tf(w[(size_t)o * KC + ch * 16 + ciL]);
        }
        __syncthreads();

#pragma unroll
        for (int ks = 0; ks < 2; ks++) {
            const unsigned* aw = sW + (ks * 8 + tg) * W_STR + mw * 16 + gid;
            unsigned a0 = aw[0];
            unsigned a1 = aw[8];
            unsigned a2 = aw[4 * W_STR];
            unsigned a3 = aw[4 * W_STR + 8];
            const unsigned* bw = sIn + (ks * 8 + tg) * IN1_STR + nhalf * 128;
#pragma unroll
            for (int nt = 0; nt < 16; nt++) {
                unsigned b0 = bw[nt * 8 + gid];
                unsigned b1 = bw[4 * IN1_STR + nt * 8 + gid];
                MMA_TF32(acc[nt][0], acc[nt][1], acc[nt][2], acc[nt][3],
                         a0, a1, a2, a3, b0, b1);
            }
        }
    }

    float* ob = out + (size_t)b * 64 * PX + p0blk;
    int o = mw * 16 + gid;
#pragma unroll
    for (int nt = 0; nt < 16; nt++) {
        int n = nhalf * 128 + nt * 8 + tg * 2;
        float2 r0 = make_float2(acc[nt][0], acc[nt][1]);
        float2 r1 = make_float2(acc[nt][2], acc[nt][3]);
        if (doRelu) {
            r0.x = fmaxf(r0.x, 0.f); r0.y = fmaxf(r0.y, 0.f);
            r1.x = fmaxf(r1.x, 0.f); r1.y = fmaxf(r1.y, 0.f);
        }
        *(float2*)(ob + (size_t)o * PX + n)       = r0;
        *(float2*)(ob + (size_t)(o + 8) * PX + n) = r1;
    }
}

// ---------------- depthwise 3x3 (v channels only) ----------------------------
__global__ void k_dw(const float* __restrict__ in, float* __restrict__ out,
                     const float* __restrict__ w) {
    int idx = blockIdx.x * 256 + threadIdx.x;
    if (idx >= NSUB) return;
    int x = idx & 127;
    int y = (idx >> 7) & 127;
    int bc = idx >> 14;
    int c = bc & 63;
    const float* wp = w + c * 9;
    const float* ip = in + (size_t)bc * PX;
    float acc = 0.f;
#pragma unroll
    for (int dy = 0; dy < 3; dy++) {
        int yy = y + dy - 1;
        if ((unsigned)yy >= 128u) continue;
#pragma unroll
        for (int dx = 0; dx < 3; dx++) {
            int xx = x + dx - 1;
            if ((unsigned)xx >= 128u) continue;
            acc = fmaf(wp[dy * 3 + dx], ip[yy * 128 + xx], acc);
        }
    }
    out[idx] = acc;
}

// ---------------- window attention (shift fused in gather/scatter) -----------
__global__ void __launch_bounds__(256) k_attn(
        const float* __restrict__ table, const float* __restrict__ temp) {
    __shared__ float qs[64][64];
    __shared__ float vsm[64][64];
    __shared__ float scl[256];
    __shared__ float tbl[900];
    __shared__ float stemp[4];

    int bw = blockIdx.x;
    int b  = bw >> 8;
    int wr = (bw >> 4) & 15;
    int wc = bw & 15;
    int tid = threadIdx.x;

    if (tid < 4) stemp[tid] = temp[tid];
    for (int l = tid; l < 900; l += 256) tbl[l] = table[l];

    for (int l = tid; l < 4096; l += 256) {
        int c = l >> 6, n = l & 63;
        int y = n >> 3, x = n & 7;
        size_t base = ((size_t)b * 64 + c) * PX;
        int qy = (wr * 8 + y + 4) & 127;
        int qx = (wc * 8 + x + 4) & 127;
        qs[c][n] = g_ll[base + qy * 128 + qx];
        int vy = wr * 8 + y, vx = wc * 8 + x;
        float vi = g_vinp[base + vy * 128 + vx];
        float ft = g_filt[base + vy * 128 + vx];
        vsm[c][n] = vi * (1.0f + ft);
    }
    __syncthreads();

    {
        int h = tid >> 6, n = tid & 63;
        float s = 0.f;
#pragma unroll
        for (int d = 0; d < 16; d++) { float v = qs[h * 16 + d][n]; s += v * v; }
        scl[tid] = 1.0f / fmaxf(sqrtf(s), 1e-12f);
    }
    __syncthreads();

    int h = tid >> 6, n = tid & 63;
    int yn = n >> 3, xn = n & 7;
    float myscl = scl[tid];
    float tph = stemp[h];

    float qn[16];
#pragma unroll
    for (int d = 0; d < 16; d++) qn[d] = qs[h * 16 + d][n] * myscl;

    float a[64];
    for (int m = 0; m < 64; m++) {
        float s = 0.f;
#pragma unroll
        for (int d = 0; d < 16; d++) s = fmaf(qn[d], qs[h * 16 + d][m], s);
        s *= scl[(h << 6) | m];
        int ym = m >> 3, xm = m & 7;
        int ridx = (yn - ym + 7) * 15 + (xn - xm + 7);
        a[m] = (s + tbl[ridx * 4 + h]) * tph;
    }

    float mx = -1e30f;
#pragma unroll
    for (int m = 0; m < 64; m++) mx = fmaxf(mx, a[m]);
    float sum = 0.f;
#pragma unroll
    for (int m = 0; m < 64; m++) { float e = expf(a[m] - mx); a[m] = e; sum += e; }
    float inv = 1.0f / sum;

    float o[16];
#pragma unroll
    for (int d = 0; d < 16; d++) o[d] = 0.f;
    for (int m = 0; m < 64; m++) {
        float am = a[m] * inv;
#pragma unroll
        for (int d = 0; d < 16; d++) o[d] = fmaf(vsm[h * 16 + d][m], am, o[d]);
    }

    int oy = (wr * 8 + yn + 4) & 127;
    int ox = (wc * 8 + xn + 4) & 127;
#pragma unroll
    for (int d = 0; d < 16; d++)
        g_z[((size_t)b * 64 + h * 16 + d) * PX + oy * 128 + ox] = o[d];
}

// ---------------- inverse Haar DWT -------------------------------------------
__global__ void k_idwt(float* __restrict__ out) {
    int idx = blockIdx.x * 256 + threadIdx.x;
    if (idx >= NSUB) return;
    int j  = idx & 127;
    int i  = (idx >> 7) & 127;
    int bc = idx >> 14;
    int b = bc >> 6, c = bc & 63;
    int p = i * 128 + j;
    float ll = g_proj[idx];
    const float* yb = g_yh + (size_t)b * 192 * PX + p;
    float lh = yb[(size_t)c * PX];
    float hl = yb[(size_t)(64 + c) * PX];
    float hh = yb[(size_t)(128 + c) * PX];
    float a  = (ll + lh + hl + hh) * 0.5f;
    float b2 = (ll - lh + hl - hh) * 0.5f;
    float c2 = (ll + lh - hl - hh) * 0.5f;
    float d2 = (ll - lh - hl + hh) * 0.5f;
    float* op = out + ((size_t)bc * 256 + 2 * i) * 256 + 2 * j;
    *(float2*)op         = make_float2(a, b2);
    *(float2*)(op + 256) = make_float2(c2, d2);
}

// ---------------- launcher ---------------------------------------------------
extern "C" void kernel_launch(void* const* d_in, const int* in_sizes, int n_in,
                              void* d_out, int out_size) {
    const float* x           = (const float*)d_in[0];
    const float* temperature = (const float*)d_in[1];
    const float* rel_bias    = (const float*)d_in[2];
    const float* w_high1     = (const float*)d_in[3];
    const float* w_high2     = (const float*)d_in[4];
    const float* w_highout   = (const float*)d_in[5];
    const float* w_qkv       = (const float*)d_in[6];
    const float* w_dwconv    = (const float*)d_in[7];
    const float* w_proj      = (const float*)d_in[8];
    float* out = (float*)d_out;

    float *p_ll, *p_lh, *p_hl, *p_hh, *p_h1, *p_filt, *p_t, *p_vinp, *p_z, *p_proj, *p_yh;
    cudaGetSymbolAddress((void**)&p_ll, g_ll);
    cudaGetSymbolAddress((void**)&p_lh, g_lh);
    cudaGetSymbolAddress((void**)&p_hl, g_hl);
    cudaGetSymbolAddress((void**)&p_hh, g_hh);
    cudaGetSymbolAddress((void**)&p_h1, g_h1);
    cudaGetSymbolAddress((void**)&p_filt, g_filt);
    cudaGetSymbolAddress((void**)&p_t, g_t);
    cudaGetSymbolAddress((void**)&p_vinp, g_vinp);
    cudaGetSymbolAddress((void**)&p_z, g_z);
    cudaGetSymbolAddress((void**)&p_proj, g_proj);
    cudaGetSymbolAddress((void**)&p_yh, g_yh);

    int nb = (NSUB + 255) / 256;
    dim3 g3(8, 8, BB);
    dim3 g11(PX / 256, BB);

    // 1. DWT
    k_dwt<<<nb, 256>>>(x);
    // 2. high1 grouped 3x3 (group0: lh, group1: hl) -> g_h1[128ch], relu
    k_conv3x3_mma<<<g3, 256>>>(p_lh, p_h1,           w_high1,               128 * PX);
    k_conv3x3_mma<<<g3, 256>>>(p_hl, p_h1 + 64 * PX, w_high1 + 64 * 64 * 9, 128 * PX);
    // 3. high2 1x1 (128->64, relu) -> filt
    k_conv1x1_mma<<<g11, 256>>>(p_h1, p_filt, w_high2, 128, 128 * PX, 1);
    // 4. qkv 1x1 (v slice only: rows 128..191) -> t
    k_conv1x1_mma<<<g11, 256>>>(p_ll, p_t, w_qkv + 128 * 64, 64, 64 * PX, 0);
    // 5. depthwise 3x3 (v channels) -> v_inp
    k_dw<<<nb, 256>>>(p_t, p_vinp, w_dwconv + 128 * 9);
    // 6. shifted-window attention (roll fused) -> z
    k_attn<<<2048, 256>>>(rel_bias, temperature);
    // 7. proj 1x1 -> proj
    k_conv1x1_mma<<<g11, 256>>>(p_z, p_proj, w_proj, 64, 64 * PX, 0);
    // 8. highout grouped 3x3 (lh/hl/hh), relu -> yh[192ch]
    k_conv3x3_mma<<<g3, 256>>>(p_lh, p_yh,            w_highout,                   192 * PX);
    k_conv3x3_mma<<<g3, 256>>>(p_hl, p_yh + 64 * PX,  w_highout + 64 * 64 * 9,     192 * PX);
    k_conv3x3_mma<<<g3, 256>>>(p_hh, p_yh + 128 * PX, w_highout + 2 * 64 * 64 * 9, 192 * PX);
    // 9. IDWT -> out
    k_idwt<<<nb, 256>>>(out);
}

// round 5
// speedup vs baseline: 3.2793x; 1.4006x over previous
#include <cuda_runtime.h>
#include <cstdint>
#include <math.h>

#define BB 8
#define CC 64
#define H2 128
#define W2 128
#define PX (H2*W2)          // 16384
#define NSUB (BB*CC*PX)     // 8388608

#define IN_STR 344          // smem stride for 18x18 input tile (bank-conflict-free)
#define IN1_STR 264         // smem stride for 256-px 1x1 tile
#define W_STR 72            // smem stride for weight o-dim

#define BUF3   7936         // words per conv3x3 buffer: 8*IN_STR(2752) + 9*8*W_STR(5184)
#define BUF1   5376         // words per conv1x1 buffer: 16*IN1_STR(4224) + 16*W_STR(1152)

#define W3_GROUP 41472      // 8 chunks * 5184 words
#define W1_H2_OFF 0         // high2: 8 chunks * 1152
#define W1_QKV_OFF 9216     // qkv:   4 chunks * 1152
#define W1_PROJ_OFF 13824   // proj:  4 chunks * 1152

// ---------------- scratch (device globals; no runtime allocation) -----------
__device__ float g_ll[NSUB];
__device__ float g_lh[NSUB];
__device__ float g_hl[NSUB];
__device__ float g_hh[NSUB];
__device__ float g_h1[2*NSUB];
__device__ float g_filt[NSUB];
__device__ float g_t[NSUB];
__device__ float g_vinp[NSUB];
__device__ float g_z[NSUB];
__device__ float g_proj[NSUB];
__device__ float g_yh[3*NSUB];
__device__ float g_w3[5*W3_GROUP];   // prepped 3x3 weights (5 groups)
__device__ float g_w1[18432];        // prepped 1x1 weights

// ---------------- helpers ----------------------------------------------------
__device__ __forceinline__ unsigned f2tf(float f) {
    unsigned u;
    asm("cvt.rna.tf32.f32 %0, %1;" : "=r"(u) : "f"(f));
    return u;
}
__device__ __forceinline__ float tf32r(float f) { return __uint_as_float(f2tf(f)); }

#define MMA_TF32(c0,c1,c2,c3,a0,a1,a2,a3,b0,b1)                                \
    asm volatile("mma.sync.aligned.m16n8k8.row.col.f32.tf32.tf32.f32 "          \
        "{%0,%1,%2,%3}, {%4,%5,%6,%7}, {%8,%9}, {%0,%1,%2,%3};\n"               \
        : "+f"(c0), "+f"(c1), "+f"(c2), "+f"(c3)                                \
        : "r"(a0), "r"(a1), "r"(a2), "r"(a3), "r"(b0), "r"(b1))

#define CP4(dst, src, sz) \
    asm volatile("cp.async.ca.shared.global [%0], [%1], 4, %2;\n" :: "r"(dst), "l"(src), "r"(sz))
#define CP16(dst, src) \
    asm volatile("cp.async.ca.shared.global [%0], [%1], 16;\n" :: "r"(dst), "l"(src))
#define CP_COMMIT()  asm volatile("cp.async.commit_group;\n")
#define CP_WAIT0()   asm volatile("cp.async.wait_group 0;\n" ::: "memory")

// ---------------- weight prep: transpose + tf32-round into smem layout -------
__global__ void k_prepw(const float* __restrict__ w_high1,
                        const float* __restrict__ w_highout,
                        const float* __restrict__ w_high2,
                        const float* __restrict__ w_qkv,
                        const float* __restrict__ w_proj) {
    int idx = blockIdx.x * 256 + threadIdx.x;
    const int total3 = 5 * W3_GROUP;
    if (idx < total3) {
        int g = idx / W3_GROUP, r = idx - g * W3_GROUP;
        int ch = r / 5184; r -= ch * 5184;
        int d = r / 576;   r -= d * 576;
        int ciL = r / 72;  int o = r - ciL * 72;
        float v = 0.f;
        if (o < 64) {
            const float* src = (g < 2) ? (w_high1 + g * 36864)
                                       : (w_highout + (g - 2) * 36864);
            v = src[((size_t)o * 64 + ch * 8 + ciL) * 9 + d];
        }
        g_w3[idx] = tf32r(v);
    }
    int i1 = idx - total3;
    if (i1 >= 0 && i1 < 18432) {
        float v = 0.f;
        if (i1 < 9216) {               // high2: KC=128
            int ch = i1 / 1152, r = i1 - ch * 1152;
            int ci = r / 72, o = r - ci * 72;
            if (o < 64) v = w_high2[(size_t)o * 128 + ch * 16 + ci];
        } else if (i1 < 13824) {       // qkv v-slice: KC=64
            int r2 = i1 - 9216;
            int ch = r2 / 1152, r = r2 - ch * 1152;
            int ci = r / 72, o = r - ci * 72;
            if (o < 64) v = w_qkv[128 * 64 + (size_t)o * 64 + ch * 16 + ci];
        } else {                       // proj: KC=64
            int r2 = i1 - 13824;
            int ch = r2 / 1152, r = r2 - ch * 1152;
            int ci = r / 72, o = r - ci * 72;
            if (o < 64) v = w_proj[(size_t)o * 64 + ch * 16 + ci];
        }
        g_w1[i1] = tf32r(v);
    }
}

// ---------------- Haar DWT (outputs tf32-rounded) ----------------------------
__global__ void k_dwt(const float* __restrict__ x) {
    int idx = blockIdx.x * 256 + threadIdx.x;
    if (idx >= NSUB) return;
    int j  = idx & 127;
    int i  = (idx >> 7) & 127;
    int bc = idx >> 14;
    const float* xp = x + ((size_t)bc * 256 + 2 * i) * 256 + 2 * j;
    float2 t0 = *(const float2*)xp;
    float2 t1 = *(const float2*)(xp + 256);
    float a = t0.x, b = t0.y, c = t1.x, d = t1.y;
    g_ll[idx] = tf32r((a + b + c + d) * 0.5f);
    g_lh[idx] = tf32r((a - b + c - d) * 0.5f);
    g_hl[idx] = tf32r((a + b - c - d) * 0.5f);
    g_hh[idx] = tf32r((a - b - c + d) * 0.5f);
}

// ---------------- 3x3 conv 64->64, tf32 MMA, cp.async double-buffered --------
__global__ void __launch_bounds__(256, 2) k_conv3x3_mma(
        const float* __restrict__ in, float* __restrict__ out,
        const float* __restrict__ wsc, int outBstride) {
    extern __shared__ unsigned sm3[];
    int tx = blockIdx.x, ty = blockIdx.y, b = blockIdx.z;
    int tid  = threadIdx.x;
    int wp   = tid >> 5;
    int lane = tid & 31;
    int gid  = lane >> 2, tg = lane & 3;
    int mw    = wp & 3;
    int nhalf = wp >> 2;
    int gx0 = tx * 16 - 1, gy0 = ty * 16 - 1;
    unsigned smaddr = (unsigned)__cvta_generic_to_shared(sm3);
    const float* ib0 = in + (size_t)b * 64 * PX;

    int posB[16];
#pragma unroll
    for (int nt = 0; nt < 16; nt++) {
        int n = nhalf * 128 + nt * 8 + gid;
        posB[nt] = (n >> 4) * 18 + (n & 15);
    }

    float acc[16][4];
#pragma unroll
    for (int t = 0; t < 16; t++) { acc[t][0] = acc[t][1] = acc[t][2] = acc[t][3] = 0.f; }

#define STAGE3(CH) {                                                            \
    int c8 = (CH);                                                              \
    unsigned base3 = smaddr + (unsigned)((c8 & 1) * BUF3) * 4u;                 \
    const float* ib = ib0 + (size_t)c8 * 8 * PX;                                \
    for (int l = tid; l < 2592; l += 256) {                                     \
        int ciL = l / 324, pos = l - ciL * 324;                                 \
        int ly = pos / 18, lx = pos - ly * 18;                                  \
        int gy = gy0 + ly, gx = gx0 + lx;                                       \
        bool ok = ((unsigned)gy < 128u) && ((unsigned)gx < 128u);               \
        const float* srcp = ok ? (ib + (size_t)ciL * PX + gy * 128 + gx) : ib;  \
        int okc = ok ? 4 : 0;                                                   \
        CP4(base3 + (unsigned)(ciL * IN_STR + pos) * 4u, srcp, okc);            \
    }                                                                           \
    const float4* ws3 = (const float4*)(wsc + (size_t)c8 * 5184);               \
    unsigned wb3 = base3 + 2752u * 4u;                                          \
    for (int l = tid; l < 1296; l += 256)                                       \
        CP16(wb3 + (unsigned)l * 16u, ws3 + l);                                 \
    CP_COMMIT(); }

    STAGE3(0);
    for (int ch = 0; ch < 8; ch++) {
        CP_WAIT0();
        __syncthreads();
        if (ch < 7) STAGE3(ch + 1);

        const unsigned* bufc = sm3 + (ch & 1) * BUF3;
        const unsigned* w_s  = bufc + 2752;
#pragma unroll
        for (int d = 0; d < 9; d++) {
            int dOff = (d / 3) * 18 + (d % 3);
            const unsigned* aw = w_s + (d * 8 + tg) * W_STR + mw * 16 + gid;
            unsigned a0 = aw[0];
            unsigned a1 = aw[8];
            unsigned a2 = aw[4 * W_STR];
            unsigned a3 = aw[4 * W_STR + 8];
            const unsigned* bw = bufc + tg * IN_STR + dOff;
#pragma unroll
            for (int nt = 0; nt < 16; nt++) {
                unsigned b0 = bw[posB[nt]];
                unsigned b1 = bw[posB[nt] + 4 * IN_STR];
                MMA_TF32(acc[nt][0], acc[nt][1], acc[nt][2], acc[nt][3],
                         a0, a1, a2, a3, b0, b1);
            }
        }
    }
#undef STAGE3

    float* ob = out + (size_t)b * outBstride;
    int o = mw * 16 + gid;
#pragma unroll
    for (int nt = 0; nt < 16; nt++) {
        int n = nhalf * 128 + nt * 8 + tg * 2;
        int gy = ty * 16 + (n >> 4), gx = tx * 16 + (n & 15);
        float* p0 = ob + (size_t)o * PX + gy * 128 + gx;
        *(float2*)p0 = make_float2(tf32r(fmaxf(acc[nt][0], 0.f)),
                                   tf32r(fmaxf(acc[nt][1], 0.f)));
        float* p1 = p0 + 8 * PX;
        *(float2*)p1 = make_float2(tf32r(fmaxf(acc[nt][2], 0.f)),
                                   tf32r(fmaxf(acc[nt][3], 0.f)));
    }
}

// ---------------- 1x1 conv, tf32 MMA, cp.async double-buffered ---------------
__global__ void __launch_bounds__(256, 2) k_conv1x1_mma(
        const float* __restrict__ in, float* __restrict__ out,
        const float* __restrict__ wsc, int nch, int inBstride, int doRelu) {
    __shared__ unsigned sm1[2][BUF1];
    int b = blockIdx.y;
    int p0blk = blockIdx.x * 256;
    int tid  = threadIdx.x;
    int wp   = tid >> 5;
    int lane = tid & 31;
    int gid  = lane >> 2, tg = lane & 3;
    int mw    = wp & 3;
    int nhalf = wp >> 2;
    unsigned smaddr = (unsigned)__cvta_generic_to_shared(&sm1[0][0]);
    const float* ib = in + (size_t)b * inBstride + p0blk;

    float acc[16][4];
#pragma unroll
    for (int t = 0; t < 16; t++) { acc[t][0] = acc[t][1] = acc[t][2] = acc[t][3] = 0.f; }

#define STAGE1(CH) {                                                            \
    int c8 = (CH);                                                              \
    unsigned base1 = smaddr + (unsigned)((c8 & 1) * BUF1) * 4u;                 \
    for (int l = tid; l < 1024; l += 256) {                                     \
        int ciL = l >> 6, p4 = l & 63;                                          \
        const float4* srcp = (const float4*)(ib + (size_t)(c8 * 16 + ciL) * PX) + p4; \
        CP16(base1 + (unsigned)(ciL * IN1_STR + p4 * 4) * 4u, srcp);            \
    }                                                                           \
    const float4* ws1 = (const float4*)(wsc + (size_t)c8 * 1152);               \
    unsigned wb1 = base1 + 4224u * 4u;                                          \
    for (int l = tid; l < 288; l += 256)                                        \
        CP16(wb1 + (unsigned)l * 16u, ws1 + l);                                 \
    CP_COMMIT(); }

    STAGE1(0);
    for (int ch = 0; ch < nch; ch++) {
        CP_WAIT0();
        __syncthreads();
        if (ch + 1 < nch) STAGE1(ch + 1);

        const unsigned* bufc = sm1[ch & 1];
        const unsigned* w_s  = bufc + 4224;
#pragma unroll
        for (int ks = 0; ks < 2; ks++) {
            const unsigned* aw = w_s + (ks * 8 + tg) * W_STR + mw * 16 + gid;
            unsigned a0 = aw[0];
            unsigned a1 = aw[8];
            unsigned a2 = aw[4 * W_STR];
            unsigned a3 = aw[4 * W_STR + 8];
            const unsigned* bw = bufc + (ks * 8 + tg) * IN1_STR + nhalf * 128;
#pragma unroll
            for (int nt = 0; nt < 16; nt++) {
                unsigned b0 = bw[nt * 8 + gid];
                unsigned b1 = bw[4 * IN1_STR + nt * 8 + gid];
                MMA_TF32(acc[nt][0], acc[nt][1], acc[nt][2], acc[nt][3],
                         a0, a1, a2, a3, b0, b1);
            }
        }
    }
#undef STAGE1

    float* ob = out + (size_t)b * 64 * PX + p0blk;
    int o = mw * 16 + gid;
#pragma unroll
    for (int nt = 0; nt < 16; nt++) {
        int n = nhalf * 128 + nt * 8 + tg * 2;
        float2 r0 = make_float2(acc[nt][0], acc[nt][1]);
        float2 r1 = make_float2(acc[nt][2], acc[nt][3]);
        if (doRelu) {
            r0.x = fmaxf(r0.x, 0.f); r0.y = fmaxf(r0.y, 0.f);
            r1.x = fmaxf(r1.x, 0.f); r1.y = fmaxf(r1.y, 0.f);
        }
        *(float2*)(ob + (size_t)o * PX + n)       = r0;
        *(float2*)(ob + (size_t)(o + 8) * PX + n) = r1;
    }
}

// ---------------- depthwise 3x3 (v channels only) ----------------------------
__global__ void k_dw(const float* __restrict__ in, float* __restrict__ out,
                     const float* __restrict__ w) {
    int idx = blockIdx.x * 256 + threadIdx.x;
    if (idx >= NSUB) return;
    int x = idx & 127;
    int y = (idx >> 7) & 127;
    int bc = idx >> 14;
    int c = bc & 63;
    const float* wp = w + c * 9;
    const float* ip = in + (size_t)bc * PX;
    float acc = 0.f;
#pragma unroll
    for (int dy = 0; dy < 3; dy++) {
        int yy = y + dy - 1;
        if ((unsigned)yy >= 128u) continue;
#pragma unroll
        for (int dx = 0; dx < 3; dx++) {
            int xx = x + dx - 1;
            if ((unsigned)xx >= 128u) continue;
            acc = fmaf(wp[dy * 3 + dx], ip[yy * 128 + xx], acc);
        }
    }
    out[idx] = acc;
}

// ---------------- window attention (shift fused; z output tf32-rounded) ------
__global__ void __launch_bounds__(256) k_attn(
        const float* __restrict__ table, const float* __restrict__ temp) {
    __shared__ float qs[64][64];
    __shared__ float vsm[64][64];
    __shared__ float scl[256];
    __shared__ float tbl[900];
    __shared__ float stemp[4];

    int bw = blockIdx.x;
    int b  = bw >> 8;
    int wr = (bw >> 4) & 15;
    int wc = bw & 15;
    int tid = threadIdx.x;

    if (tid < 4) stemp[tid] = temp[tid];
    for (int l = tid; l < 900; l += 256) tbl[l] = table[l];

    for (int l = tid; l < 4096; l += 256) {
        int c = l >> 6, n = l & 63;
        int y = n >> 3, x = n & 7;
        size_t base = ((size_t)b * 64 + c) * PX;
        int qy = (wr * 8 + y + 4) & 127;
        int qx = (wc * 8 + x + 4) & 127;
        qs[c][n] = g_ll[base + qy * 128 + qx];
        int vy = wr * 8 + y, vx = wc * 8 + x;
        float vi = g_vinp[base + vy * 128 + vx];
        float ft = g_filt[base + vy * 128 + vx];
        vsm[c][n] = vi * (1.0f + ft);
    }
    __syncthreads();

    {
        int h = tid >> 6, n = tid & 63;
        float s = 0.f;
#pragma unroll
        for (int d = 0; d < 16; d++) { float v = qs[h * 16 + d][n]; s += v * v; }
        scl[tid] = 1.0f / fmaxf(sqrtf(s), 1e-12f);
    }
    __syncthreads();

    int h = tid >> 6, n = tid & 63;
    int yn = n >> 3, xn = n & 7;
    float myscl = scl[tid];
    float tph = stemp[h];

    float qn[16];
#pragma unroll
    for (int d = 0; d < 16; d++) qn[d] = qs[h * 16 + d][n] * myscl;

    float a[64];
    for (int m = 0; m < 64; m++) {
        float s = 0.f;
#pragma unroll
        for (int d = 0; d < 16; d++) s = fmaf(qn[d], qs[h * 16 + d][m], s);
        s *= scl[(h << 6) | m];
        int ym = m >> 3, xm = m & 7;
        int ridx = (yn - ym + 7) * 15 + (xn - xm + 7);
        a[m] = (s + tbl[ridx * 4 + h]) * tph;
    }

    float mx = -1e30f;
#pragma unroll
    for (int m = 0; m < 64; m++) mx = fmaxf(mx, a[m]);
    float sum = 0.f;
#pragma unroll
    for (int m = 0; m < 64; m++) { float e = expf(a[m] - mx); a[m] = e; sum += e; }
    float inv = 1.0f / sum;

    float o[16];
#pragma unroll
    for (int d = 0; d < 16; d++) o[d] = 0.f;
    for (int m = 0; m < 64; m++) {
        float am = a[m] * inv;
#pragma unroll
        for (int d = 0; d < 16; d++) o[d] = fmaf(vsm[h * 16 + d][m], am, o[d]);
    }

    int oy = (wr * 8 + yn + 4) & 127;
    int ox = (wc * 8 + xn + 4) & 127;
#pragma unroll
    for (int d = 0; d < 16; d++)
        g_z[((size_t)b * 64 + h * 16 + d) * PX + oy * 128 + ox] = tf32r(o[d]);
}

// ---------------- inverse Haar DWT -------------------------------------------
__global__ void k_idwt(float* __restrict__ out) {
    int idx = blockIdx.x * 256 + threadIdx.x;
    if (idx >= NSUB) return;
    int j  = idx & 127;
    int i  = (idx >> 7) & 127;
    int bc = idx >> 14;
    int b = bc >> 6, c = bc & 63;
    int p = i * 128 + j;
    float ll = g_proj[idx];
    const float* yb = g_yh + (size_t)b * 192 * PX + p;
    float lh = yb[(size_t)c * PX];
    float hl = yb[(size_t)(64 + c) * PX];
    float hh = yb[(size_t)(128 + c) * PX];
    float a  = (ll + lh + hl + hh) * 0.5f;
    float b2 = (ll - lh + hl - hh) * 0.5f;
    float c2 = (ll + lh - hl - hh) * 0.5f;
    float d2 = (ll - lh - hl + hh) * 0.5f;
    float* op = out + ((size_t)bc * 256 + 2 * i) * 256 + 2 * j;
    *(float2*)op         = make_float2(a, b2);
    *(float2*)(op + 256) = make_float2(c2, d2);
}

// ---------------- launcher ---------------------------------------------------
extern "C" void kernel_launch(void* const* d_in, const int* in_sizes, int n_in,
                              void* d_out, int out_size) {
    const float* x           = (const float*)d_in[0];
    const float* temperature = (const float*)d_in[1];
    const float* rel_bias    = (const float*)d_in[2];
    const float* w_high1     = (const float*)d_in[3];
    const float* w_high2     = (const float*)d_in[4];
    const float* w_highout   = (const float*)d_in[5];
    const float* w_qkv       = (const float*)d_in[6];
    const float* w_dwconv    = (const float*)d_in[7];
    const float* w_proj      = (const float*)d_in[8];
    float* out = (float*)d_out;

    float *p_ll, *p_lh, *p_hl, *p_hh, *p_h1, *p_filt, *p_t, *p_vinp, *p_z, *p_proj, *p_yh, *p_w3, *p_w1;
    cudaGetSymbolAddress((void**)&p_ll, g_ll);
    cudaGetSymbolAddress((void**)&p_lh, g_lh);
    cudaGetSymbolAddress((void**)&p_hl, g_hl);
    cudaGetSymbolAddress((void**)&p_hh, g_hh);
    cudaGetSymbolAddress((void**)&p_h1, g_h1);
    cudaGetSymbolAddress((void**)&p_filt, g_filt);
    cudaGetSymbolAddress((void**)&p_t, g_t);
    cudaGetSymbolAddress((void**)&p_vinp, g_vinp);
    cudaGetSymbolAddress((void**)&p_z, g_z);
    cudaGetSymbolAddress((void**)&p_proj, g_proj);
    cudaGetSymbolAddress((void**)&p_yh, g_yh);
    cudaGetSymbolAddress((void**)&p_w3, g_w3);
    cudaGetSymbolAddress((void**)&p_w1, g_w1);

    static int smem_set = 0;
    if (!smem_set) {
        cudaFuncSetAttribute(k_conv3x3_mma,
            cudaFuncAttributeMaxDynamicSharedMemorySize, 2 * BUF3 * 4);
        smem_set = 1;
    }

    int nb = (NSUB + 255) / 256;
    dim3 g3(8, 8, BB);
    dim3 g11(PX / 256, BB);
    int dyn3 = 2 * BUF3 * 4;

    // 0. weight prep (transpose + tf32 round into MMA-ready layout)
    k_prepw<<<(5 * W3_GROUP + 18432 + 255) / 256, 256>>>(w_high1, w_highout, w_high2, w_qkv, w_proj);
    // 1. DWT
    k_dwt<<<nb, 256>>>(x);
    // 2. high1 grouped 3x3 -> g_h1[128ch], relu
    k_conv3x3_mma<<<g3, 256, dyn3>>>(p_lh, p_h1,           p_w3,                128 * PX);
    k_conv3x3_mma<<<g3, 256, dyn3>>>(p_hl, p_h1 + 64 * PX, p_w3 + W3_GROUP,     128 * PX);
    // 3. high2 1x1 (128->64, relu) -> filt
    k_conv1x1_mma<<<g11, 256>>>(p_h1, p_filt, p_w1 + W1_H2_OFF,  8, 128 * PX, 1);
    // 4. qkv 1x1 (v slice only) -> t
    k_conv1x1_mma<<<g11, 256>>>(p_ll, p_t,    p_w1 + W1_QKV_OFF, 4, 64 * PX, 0);
    // 5. depthwise 3x3 (v channels) -> v_inp
    k_dw<<<nb, 256>>>(p_t, p_vinp, w_dwconv + 128 * 9);
    // 6. shifted-window attention (roll fused) -> z
    k_attn<<<2048, 256>>>(rel_bias, temperature);
    // 7. proj 1x1 -> proj
    k_conv1x1_mma<<<g11, 256>>>(p_z, p_proj,  p_w1 + W1_PROJ_OFF, 4, 64 * PX, 0);
    // 8. highout grouped 3x3 (lh/hl/hh), relu -> yh[192ch]
    k_conv3x3_mma<<<g3, 256, dyn3>>>(p_lh, p_yh,            p_w3 + 2 * W3_GROUP, 192 * PX);
    k_conv3x3_mma<<<g3, 256, dyn3>>>(p_hl, p_yh + 64 * PX,  p_w3 + 3 * W3_GROUP, 192 * PX);
    k_conv3x3_mma<<<g3, 256, dyn3>>>(p_hh, p_yh + 128 * PX, p_w3 + 4 * W3_GROUP, 192 * PX);
    // 9. IDWT -> out
    k_idwt<<<nb, 256>>>(out);
}

// round 7
// speedup vs baseline: 3.4290x; 1.0457x over previous
#include <cuda_runtime.h>
#include <cstdint>
#include <math.h>

#define BB 8
#define CC 64
#define H2 128
#define W2 128
#define PX (H2*W2)          // 16384
#define NSUB (BB*CC*PX)     // 8388608

// conv3x3 smem image: [ci][18 rows][24 cols], col c <-> gx = tx*16-4+c
#define ROW_STR 24
#define CI_STR 440          // 18*24=432, padded to 440 (mod 32 = 24 -> banks {0,24,16,8})
#define IMG3 3520           // 8 * CI_STR
#define WCH3 4608           // weights per chunk: 9*64*8
#define BUF3 (IMG3 + WCH3)  // 8128 words per buffer

#define IN1_STR 264
#define W_STR 72
#define BUF1 5376

#define W3_GROUP 36864      // 8 chunks * 4608
#define W1_H2_OFF 0
#define W1_QKV_OFF 9216
#define W1_PROJ_OFF 13824

// ---------------- scratch (device globals; no runtime allocation) -----------
__device__ float g_ll[NSUB];
__device__ float g_lh[NSUB];
__device__ float g_hl[NSUB];
__device__ float g_hh[NSUB];
__device__ float g_h1[2*NSUB];
__device__ float g_filt[NSUB];
__device__ float g_t[NSUB];
__device__ float g_z[NSUB];
__device__ float g_proj[NSUB];
__device__ float g_yh[3*NSUB];
__device__ float g_w3[5*W3_GROUP];
__device__ float g_w1[18432];

// ---------------- helpers ----------------------------------------------------
__device__ __forceinline__ unsigned f2tf(float f) {
    unsigned u;
    asm("cvt.rna.tf32.f32 %0, %1;" : "=r"(u) : "f"(f));
    return u;
}
__device__ __forceinline__ float tf32r(float f) { return __uint_as_float(f2tf(f)); }

#define MMA_TF32(c0,c1,c2,c3,a0,a1,a2,a3,b0,b1)                                \
    asm volatile("mma.sync.aligned.m16n8k8.row.col.f32.tf32.tf32.f32 "          \
        "{%0,%1,%2,%3}, {%4,%5,%6,%7}, {%8,%9}, {%0,%1,%2,%3};\n"               \
        : "+f"(c0), "+f"(c1), "+f"(c2), "+f"(c3)                                \
        : "r"(a0), "r"(a1), "r"(a2), "r"(a3), "r"(b0), "r"(b1))

#define CP16(dst, src) \
    asm volatile("cp.async.ca.shared.global [%0], [%1], 16;\n" :: "r"(dst), "l"(src))
#define CP16Z(dst, src, sz) \
    asm volatile("cp.async.ca.shared.global [%0], [%1], 16, %2;\n" :: "r"(dst), "l"(src), "r"(sz))
#define CP_COMMIT()  asm volatile("cp.async.commit_group;\n")
#define CP_WAIT0()   asm volatile("cp.async.wait_group 0;\n" ::: "memory")

// ---------------- weight prep ------------------------------------------------
// 3x3 layout per group/chunk: word = (d*64 + o)*8 + 2*slot + par
//   slot = ((ci&3) + (o>>2)) & 3, par = ci>>2   (ci = in-chunk channel 0..7)
__global__ void k_prepw(const float* __restrict__ w_high1,
                        const float* __restrict__ w_highout,
                        const float* __restrict__ w_high2,
                        const float* __restrict__ w_qkv,
                        const float* __restrict__ w_proj) {
    int idx = blockIdx.x * 256 + threadIdx.x;
    const int total3 = 5 * W3_GROUP;   // 184320
    if (idx < total3) {
        int g = idx / W3_GROUP, r = idx - g * W3_GROUP;
        int ch = r / WCH3;  int w = r - ch * WCH3;
        int d = w / 512;    int rem = w - d * 512;
        int o = rem >> 3;   int s = rem & 7;
        int slot = s >> 1, par = s & 1;
        int ci = par * 4 + ((slot - (o >> 2)) & 3);
        const float* src = (g < 2) ? (w_high1 + g * 36864)
                                   : (w_highout + (g - 2) * 36864);
        float v = src[((size_t)o * 64 + ch * 8 + ci) * 9 + d];
        g_w3[idx] = tf32r(v);
    }
    int i1 = idx - total3;
    if (i1 >= 0 && i1 < 18432) {
        float v = 0.f;
        if (i1 < 9216) {               // high2: KC=128
            int ch = i1 / 1152, r = i1 - ch * 1152;
            int ci = r / 72, o = r - ci * 72;
            if (o < 64) v = w_high2[(size_t)o * 128 + ch * 16 + ci];
        } else if (i1 < 13824) {       // qkv v-slice: KC=64
            int r2 = i1 - 9216;
            int ch = r2 / 1152, r = r2 - ch * 1152;
            int ci = r / 72, o = r - ci * 72;
            if (o < 64) v = w_qkv[128 * 64 + (size_t)o * 64 + ch * 16 + ci];
        } else {                       // proj: KC=64
            int r2 = i1 - 13824;
            int ch = r2 / 1152, r = r2 - ch * 1152;
            int ci = r / 72, o = r - ci * 72;
            if (o < 64) v = w_proj[(size_t)o * 64 + ch * 16 + ci];
        }
        g_w1[i1] = tf32r(v);
    }
}

// ---------------- Haar DWT (outputs tf32-rounded) ----------------------------
__global__ void k_dwt(const float* __restrict__ x) {
    int idx = blockIdx.x * 256 + threadIdx.x;
    if (idx >= NSUB) return;
    int j  = idx & 127;
    int i  = (idx >> 7) & 127;
    int bc = idx >> 14;
    const float* xp = x + ((size_t)bc * 256 + 2 * i) * 256 + 2 * j;
    float2 t0 = *(const float2*)xp;
    float2 t1 = *(const float2*)(xp + 256);
    float a = t0.x, b = t0.y, c = t1.x, d = t1.y;
    g_ll[idx] = tf32r((a + b + c + d) * 0.5f);
    g_lh[idx] = tf32r((a - b + c - d) * 0.5f);
    g_hl[idx] = tf32r((a + b - c - d) * 0.5f);
    g_hh[idx] = tf32r((a - b - c + d) * 0.5f);
}

// ---------------- merged 3x3 convs, tf32 MMA, 16B-staged double buffer -------
// grid (8,8,40): z = grp*8 + b. grp: 0 lh->h1[0:64], 1 hl->h1[64:128],
// 2 lh->yh[0:64], 3 hl->yh[64:128], 4 hh->yh[128:192]. All relu.
__global__ void __launch_bounds__(256, 2) k_conv3x3_mma() {
    extern __shared__ unsigned sm3[];
    int tx = blockIdx.x, ty = blockIdx.y;
    int bz = blockIdx.z;
    int grp = bz >> 3, b = bz & 7;

    const float* in;
    float* out;
    int ostr;
    if (grp == 0)      { in = g_lh; out = g_h1;                      ostr = 128 * PX; }
    else if (grp == 1) { in = g_hl; out = g_h1 + (size_t)64 * PX;    ostr = 128 * PX; }
    else if (grp == 2) { in = g_lh; out = g_yh;                      ostr = 192 * PX; }
    else if (grp == 3) { in = g_hl; out = g_yh + (size_t)64 * PX;    ostr = 192 * PX; }
    else               { in = g_hh; out = g_yh + (size_t)128 * PX;   ostr = 192 * PX; }
    const float* wsc = g_w3 + (size_t)grp * W3_GROUP;

    int tid  = threadIdx.x;
    int wp   = tid >> 5;
    int lane = tid & 31;
    int gid  = lane >> 2, tg = lane & 3;
    int mw    = wp & 3;
    int nhalf = wp >> 2;
    int gy0  = ty * 16 - 1;       // smem row r <-> gy0 + r
    int gx0s = tx * 16 - 4;       // smem col 0 <-> gx0s
    unsigned smaddr = (unsigned)__cvta_generic_to_shared(sm3);
    const float* ib0 = in + (size_t)b * 64 * PX;

    int posB[16];
#pragma unroll
    for (int nt = 0; nt < 16; nt++) {
        int n = nhalf * 128 + nt * 8 + gid;
        posB[nt] = (n >> 4) * ROW_STR + (n & 15) + 3;
    }

    float acc[16][4];
#pragma unroll
    for (int t = 0; t < 16; t++) { acc[t][0] = acc[t][1] = acc[t][2] = acc[t][3] = 0.f; }

    // image: 8 ci x 18 rows x 6 segments of 4 floats (16B each) = 864 copies
#define STAGE3(CH) {                                                            \
    int c8 = (CH);                                                              \
    unsigned base3 = smaddr + (unsigned)((c8 & 1) * BUF3) * 4u;                 \
    const float* ib = ib0 + (size_t)c8 * 8 * PX;                                \
    for (int l = tid; l < 864; l += 256) {                                      \
        int ciL = l / 108, rr = l - ciL * 108;                                  \
        int row = rr / 6, s = rr - row * 6;                                     \
        int gy = gy0 + row;                                                     \
        int gxs = gx0s + s * 4;                                                 \
        bool ok = ((unsigned)gy < 128u) && ((unsigned)gxs <= 124u);             \
        const float* srcp = ib + (size_t)ciL * PX + (ok ? (gy * 128 + gxs) : 0);\
        int sz = ok ? 16 : 0;                                                   \
        CP16Z(base3 + (unsigned)(ciL * CI_STR + row * ROW_STR + s * 4) * 4u,    \
              srcp, sz);                                                        \
    }                                                                           \
    const float4* ws3 = (const float4*)(wsc + (size_t)c8 * WCH3);               \
    unsigned wb3 = base3 + (unsigned)IMG3 * 4u;                                 \
    for (int l = tid; l < 1152; l += 256)                                       \
        CP16(wb3 + (unsigned)l * 16u, ws3 + l);                                 \
    CP_COMMIT(); }

    STAGE3(0);
    int o = mw * 16 + gid;
    int slotA  = (tg + (o >> 2)) & 3;
    int slotA8 = (tg + ((o + 8) >> 2)) & 3;

    for (int ch = 0; ch < 8; ch++) {
        CP_WAIT0();
        __syncthreads();
        if (ch < 7) STAGE3(ch + 1);

        const unsigned* bufc = sm3 + (ch & 1) * BUF3;
        const unsigned* w_s  = bufc + IMG3;
#pragma unroll
        for (int d = 0; d < 9; d++) {
            const unsigned* ap = w_s + (d * 64 + o) * 8;
            uint2 A02 = *(const uint2*)(ap + 2 * slotA);
            uint2 A13 = *(const uint2*)(ap + 64 + 2 * slotA8);
            unsigned a0 = A02.x, a2 = A02.y, a1 = A13.x, a3 = A13.y;
            int dOff = (d / 3) * ROW_STR + (d % 3);
            const unsigned* bw = bufc + tg * CI_STR + dOff;
#pragma unroll
            for (int nt = 0; nt < 16; nt++) {
                unsigned b0 = bw[posB[nt]];
                unsigned b1 = bw[posB[nt] + 4 * CI_STR];
                MMA_TF32(acc[nt][0], acc[nt][1], acc[nt][2], acc[nt][3],
                         a0, a1, a2, a3, b0, b1);
            }
        }
    }
#undef STAGE3

    float* ob = out + (size_t)b * ostr;
#pragma unroll
    for (int nt = 0; nt < 16; nt++) {
        int n = nhalf * 128 + nt * 8 + tg * 2;
        int gy = ty * 16 + (n >> 4), gx = tx * 16 + (n & 15);
        float* p0 = ob + (size_t)o * PX + gy * 128 + gx;
        *(float2*)p0 = make_float2(tf32r(fmaxf(acc[nt][0], 0.f)),
                                   tf32r(fmaxf(acc[nt][1], 0.f)));
        float* p1 = p0 + 8 * PX;
        *(float2*)p1 = make_float2(tf32r(fmaxf(acc[nt][2], 0.f)),
                                   tf32r(fmaxf(acc[nt][3], 0.f)));
    }
}

// ---------------- 1x1 conv, tf32 MMA, cp.async double-buffered ---------------
__global__ void __launch_bounds__(256, 2) k_conv1x1_mma(
        const float* __restrict__ in, float* __restrict__ out,
        const float* __restrict__ wsc, int nch, int inBstride, int doRelu) {
    __shared__ unsigned sm1[2][BUF1];
    int b = blockIdx.y;
    int p0blk = blockIdx.x * 256;
    int tid  = threadIdx.x;
    int wp   = tid >> 5;
    int lane = tid & 31;
    int gid  = lane >> 2, tg = lane & 3;
    int mw    = wp & 3;
    int nhalf = wp >> 2;
    unsigned smaddr = (unsigned)__cvta_generic_to_shared(&sm1[0][0]);
    const float* ib = in + (size_t)b * inBstride + p0blk;

    float acc[16][4];
#pragma unroll
    for (int t = 0; t < 16; t++) { acc[t][0] = acc[t][1] = acc[t][2] = acc[t][3] = 0.f; }

#define STAGE1(CH) {                                                            \
    int c8 = (CH);                                                              \
    unsigned base1 = smaddr + (unsigned)((c8 & 1) * BUF1) * 4u;                 \
    for (int l = tid; l < 1024; l += 256) {                                     \
        int ciL = l >> 6, p4 = l & 63;                                          \
        const float4* srcp = (const float4*)(ib + (size_t)(c8 * 16 + ciL) * PX) + p4; \
        CP16(base1 + (unsigned)(ciL * IN1_STR + p4 * 4) * 4u, srcp);            \
    }                                                                           \
    const float4* ws1 = (const float4*)(wsc + (size_t)c8 * 1152);               \
    unsigned wb1 = base1 + 4224u * 4u;                                          \
    for (int l = tid; l < 288; l += 256)                                        \
        CP16(wb1 + (unsigned)l * 16u, ws1 + l);                                 \
    CP_COMMIT(); }

    STAGE1(0);
    for (int ch = 0; ch < nch; ch++) {
        CP_WAIT0();
        __syncthreads();
        if (ch + 1 < nch) STAGE1(ch + 1);

        const unsigned* bufc = sm1[ch & 1];
        const unsigned* w_s  = bufc + 4224;
#pragma unroll
        for (int ks = 0; ks < 2; ks++) {
            const unsigned* aw = w_s + (ks * 8 + tg) * W_STR + mw * 16 + gid;
            unsigned a0 = aw[0];
            unsigned a1 = aw[8];
            unsigned a2 = aw[4 * W_STR];
            unsigned a3 = aw[4 * W_STR + 8];
            const unsigned* bw = bufc + (ks * 8 + tg) * IN1_STR + nhalf * 128;
#pragma unroll
            for (int nt = 0; nt < 16; nt++) {
                unsigned b0 = bw[nt * 8 + gid];
                unsigned b1 = bw[4 * IN1_STR + nt * 8 + gid];
                MMA_TF32(acc[nt][0], acc[nt][1], acc[nt][2], acc[nt][3],
                         a0, a1, a2, a3, b0, b1);
            }
        }
    }
#undef STAGE1

    float* ob = out + (size_t)b * 64 * PX + p0blk;
    int o = mw * 16 + gid;
#pragma unroll
    for (int nt = 0; nt < 16; nt++) {
        int n = nhalf * 128 + nt * 8 + tg * 2;
        float2 r0 = make_float2(acc[nt][0], acc[nt][1]);
        float2 r1 = make_float2(acc[nt][2], acc[nt][3]);
        if (doRelu) {
            r0.x = fmaxf(r0.x, 0.f); r0.y = fmaxf(r0.y, 0.f);
            r1.x = fmaxf(r1.x, 0.f); r1.y = fmaxf(r1.y, 0.f);
        }
        *(float2*)(ob + (size_t)o * PX + n)       = r0;
        *(float2*)(ob + (size_t)(o + 8) * PX + n) = r1;
    }
}

// ---------------- window attention + fused depthwise 3x3 ---------------------
// dynamic smem: qs[4096] vsm[4096] tp[6400] scl[256] tbl[900] stemp[4] sdw[576]
#define ATTN_SMEM_WORDS 16328
__global__ void __launch_bounds__(256) k_attn(
        const float* __restrict__ table, const float* __restrict__ temp,
        const float* __restrict__ wdw) {
    extern __shared__ float sA[];
    float* qs    = sA;
    float* vsm   = sA + 4096;
    float* tp    = sA + 8192;
    float* scl   = sA + 14592;
    float* tbl   = sA + 14848;
    float* stemp = sA + 15748;
    float* sdw   = sA + 15752;

    int bw = blockIdx.x;
    int b  = bw >> 8;
    int wr = (bw >> 4) & 15;
    int wc = bw & 15;
    int tid = threadIdx.x;

    if (tid < 4) stemp[tid] = temp[tid];
    for (int l = tid; l < 900; l += 256) tbl[l] = table[l];
    for (int l = tid; l < 576; l += 256) sdw[l] = wdw[l];

    // t-patch (10x10 per channel) for depthwise
    for (int l = tid; l < 6400; l += 256) {
        int c = l / 100, p = l - c * 100;
        int py = p / 10, px = p - py * 10;
        int gy = wr * 8 - 1 + py, gx = wc * 8 - 1 + px;
        float v = 0.f;
        if ((unsigned)gy < 128u && (unsigned)gx < 128u)
            v = g_t[((size_t)b * 64 + c) * PX + gy * 128 + gx];
        tp[l] = v;
    }
    // q (shifted ll)
    for (int l = tid; l < 4096; l += 256) {
        int c = l >> 6, n = l & 63;
        int y = n >> 3, x = n & 7;
        int qy = (wr * 8 + y + 4) & 127;
        int qx = (wc * 8 + x + 4) & 127;
        qs[l] = g_ll[((size_t)b * 64 + c) * PX + qy * 128 + qx];
    }
    __syncthreads();

    // depthwise + filt -> vsm
    for (int l = tid; l < 4096; l += 256) {
        int c = l >> 6, n = l & 63;
        int y = n >> 3, x = n & 7;
        const float* tc = tp + c * 100;
        const float* wc9 = sdw + c * 9;
        float a0 = 0.f;
#pragma unroll
        for (int dy = 0; dy < 3; dy++)
#pragma unroll
            for (int dx = 0; dx < 3; dx++)
                a0 = fmaf(wc9[dy * 3 + dx], tc[(y + dy) * 10 + x + dx], a0);
        float ft = g_filt[((size_t)b * 64 + c) * PX + (wr * 8 + y) * 128 + wc * 8 + x];
        vsm[l] = a0 * (1.0f + ft);
    }
    __syncthreads();

    {
        int h = tid >> 6, n = tid & 63;
        float s = 0.f;
#pragma unroll
        for (int d = 0; d < 16; d++) { float v = qs[(h * 16 + d) * 64 + n]; s += v * v; }
        scl[tid] = 1.0f / fmaxf(sqrtf(s), 1e-12f);
    }
    __syncthreads();

    int h = tid >> 6, n = tid & 63;
    int yn = n >> 3, xn = n & 7;
    float myscl = scl[tid];
    float tph = stemp[h];

    float qn[16];
#pragma unroll
    for (int d = 0; d < 16; d++) qn[d] = qs[(h * 16 + d) * 64 + n] * myscl;

    float a[64];
    for (int m = 0; m < 64; m++) {
        float s = 0.f;
#pragma unroll
        for (int d = 0; d < 16; d++) s = fmaf(qn[d], qs[(h * 16 + d) * 64 + m], s);
        s *= scl[(h << 6) | m];
        int ym = m >> 3, xm = m & 7;
        int ridx = (yn - ym + 7) * 15 + (xn - xm + 7);
        a[m] = (s + tbl[ridx * 4 + h]) * tph;
    }

    float mx = -1e30f;
#pragma unroll
    for (int m = 0; m < 64; m++) mx = fmaxf(mx, a[m]);
    float sum = 0.f;
#pragma unroll
    for (int m = 0; m < 64; m++) { float e = expf(a[m] - mx); a[m] = e; sum += e; }
    float inv = 1.0f / sum;

    float o[16];
#pragma unroll
    for (int d = 0; d < 16; d++) o[d] = 0.f;
    for (int m = 0; m < 64; m++) {
        float am = a[m] * inv;
#pragma unroll
        for (int d = 0; d < 16; d++) o[d] = fmaf(vsm[(h * 16 + d) * 64 + m], am, o[d]);
    }

    int oy = (wr * 8 + yn + 4) & 127;
    int ox = (wc * 8 + xn + 4) & 127;
#pragma unroll
    for (int d = 0; d < 16; d++)
        g_z[((size_t)b * 64 + h * 16 + d) * PX + oy * 128 + ox] = tf32r(o[d]);
}

// ---------------- inverse Haar DWT -------------------------------------------
__global__ void k_idwt(float* __restrict__ out) {
    int idx = blockIdx.x * 256 + threadIdx.x;
    if (idx >= NSUB) return;
    int j  = idx & 127;
    int i  = (idx >> 7) & 127;
    int bc = idx >> 14;
    int b = bc >> 6, c = bc & 63;
    int p = i * 128 + j;
    float ll = g_proj[idx];
    const float* yb = g_yh + (size_t)b * 192 * PX + p;
    float lh = yb[(size_t)c * PX];
    float hl = yb[(size_t)(64 + c) * PX];
    float hh = yb[(size_t)(128 + c) * PX];
    float a  = (ll + lh + hl + hh) * 0.5f;
    float b2 = (ll - lh + hl - hh) * 0.5f;
    float c2 = (ll + lh - hl - hh) * 0.5f;
    float d2 = (ll - lh - hl + hh) * 0.5f;
    float* op = out + ((size_t)bc * 256 + 2 * i) * 256 + 2 * j;
    *(float2*)op         = make_float2(a, b2);
    *(float2*)(op + 256) = make_float2(c2, d2);
}

// ---------------- launcher ---------------------------------------------------
extern "C" void kernel_launch(void* const* d_in, const int* in_sizes, int n_in,
                              void* d_out, int out_size) {
    const float* x           = (const float*)d_in[0];
    const float* temperature = (const float*)d_in[1];
    const float* rel_bias    = (const float*)d_in[2];
    const float* w_high1     = (const float*)d_in[3];
    const float* w_high2     = (const float*)d_in[4];
    const float* w_highout   = (const float*)d_in[5];
    const float* w_qkv       = (const float*)d_in[6];
    const float* w_dwconv    = (const float*)d_in[7];
    const float* w_proj      = (const float*)d_in[8];
    float* out = (float*)d_out;

    float *p_ll, *p_h1, *p_filt, *p_t, *p_z, *p_proj, *p_w1;
    cudaGetSymbolAddress((void**)&p_ll, g_ll);
    cudaGetSymbolAddress((void**)&p_h1, g_h1);
    cudaGetSymbolAddress((void**)&p_filt, g_filt);
    cudaGetSymbolAddress((void**)&p_t, g_t);
    cudaGetSymbolAddress((void**)&p_z, g_z);
    cudaGetSymbolAddress((void**)&p_proj, g_proj);
    cudaGetSymbolAddress((void**)&p_w1, g_w1);

    static int smem_set = 0;
    if (!smem_set) {
        cudaFuncSetAttribute(k_conv3x3_mma,
            cudaFuncAttributeMaxDynamicSharedMemorySize, 2 * BUF3 * 4);
        cudaFuncSetAttribute(k_attn,
            cudaFuncAttributeMaxDynamicSharedMemorySize, ATTN_SMEM_WORDS * 4);
        smem_set = 1;
    }

    int nb = (NSUB + 255) / 256;
    dim3 g3(8, 8, 40);
    dim3 g11(PX / 256, BB);
    int dyn3 = 2 * BUF3 * 4;
    int dynA = ATTN_SMEM_WORDS * 4;

    // 0. weight prep
    k_prepw<<<(5 * W3_GROUP + 18432 + 255) / 256, 256>>>(w_high1, w_highout, w_high2, w_qkv, w_proj);
    // 1. DWT
    k_dwt<<<nb, 256>>>(x);
    // 2. all five grouped 3x3 convs (high1 x2 + highout x3), relu, merged
    k_conv3x3_mma<<<g3, 256, dyn3>>>();
    // 3. high2 1x1 (128->64, relu) -> filt
    k_conv1x1_mma<<<g11, 256>>>(p_h1, p_filt, p_w1 + W1_H2_OFF,  8, 128 * PX, 1);
    // 4. qkv 1x1 (v slice only) -> t
    k_conv1x1_mma<<<g11, 256>>>(p_ll, p_t,    p_w1 + W1_QKV_OFF, 4, 64 * PX, 0);
    // 5. attention with fused depthwise (roll fused) -> z
    k_attn<<<2048, 256, dynA>>>(rel_bias, temperature, w_dwconv + 128 * 9);
    // 6. proj 1x1 -> proj
    k_conv1x1_mma<<<g11, 256>>>(p_z, p_proj,  p_w1 + W1_PROJ_OFF, 4, 64 * PX, 0);
    // 7. IDWT -> out
    k_idwt<<<nb, 256>>>(out);
}